// round 16
// baseline (speedup 1.0000x reference)
#include <cuda_runtime.h>
#include <cstdint>

#define NROWS 1024
#define MROWS 1024
#define DIM   512
#define DHALF 256

__device__ float g_hx[NROWS * DIM];
__device__ float g_hy[MROWS * DIM];
__device__ float g_xr[NROWS * DIM];     // tf32-rounded x
__device__ float g_yr[MROWS * DIM];     // tf32-rounded y
__device__ float g_Wr[2 * DIM * DIM];   // tf32-rounded W1 (k-major)

typedef unsigned long long u64;

#define ADD2(d, a, b) \
    asm("add.rn.f32x2 %0, %1, %2;" : "=l"(d) : "l"(a), "l"(b))
#define FMA2(d, a, b, c) \
    asm("fma.rn.f32x2 %0, %1, %2, %3;" : "=l"(d) : "l"(a), "l"(b), "l"(c))

__device__ __forceinline__ u64 relu2(u64 s) {
    unsigned int lo, hi;
    asm("mov.b64 {%0,%1}, %2;" : "=r"(lo), "=r"(hi) : "l"(s));
    float f0 = fmaxf(__uint_as_float(lo), 0.0f);
    float f1 = fmaxf(__uint_as_float(hi), 0.0f);
    u64 r;
    asm("mov.b64 %0, {%1,%2};"
        : "=l"(r) : "r"(__float_as_uint(f0)), "r"(__float_as_uint(f1)));
    return r;
}

__device__ __forceinline__ float hsum2(u64 s) {
    unsigned int lo, hi;
    asm("mov.b64 {%0,%1}, %2;" : "=r"(lo), "=r"(hi) : "l"(s));
    return __uint_as_float(lo) + __uint_as_float(hi);
}

__device__ __forceinline__ float to_tf32(float f) {
    uint32_t u;
    asm("cvt.rna.tf32.f32 %0, %1;" : "=r"(u) : "f"(f));
    return __uint_as_float(u);
}

__device__ __forceinline__ void cpa16_ca(uint32_t s, const void* g) {
    asm volatile("cp.async.ca.shared.global [%0], [%1], 16;" :: "r"(s), "l"(g));
}
#define CP_COMMIT() asm volatile("cp.async.commit_group;" ::: "memory")
#define CP_WAIT(n)  asm volatile("cp.async.wait_group %0;" :: "n"(n) : "memory")

#define MMA_TF32(c, a, b) \
    asm("mma.sync.aligned.m16n8k8.row.col.f32.tf32.tf32.f32 " \
        "{%0,%1,%2,%3}, {%4,%5,%6,%7}, {%8,%9}, {%0,%1,%2,%3};" \
        : "+f"((c)[0]), "+f"((c)[1]), "+f"((c)[2]), "+f"((c)[3]) \
        : "r"((a)[0]), "r"((a)[1]), "r"((a)[2]), "r"((a)[3]), \
          "r"((b)[0]), "r"((b)[1]))

// -------------------------------------------------------------------------
// Pre-round x, y, W1 to tf32 and zero the output buffer.
// -------------------------------------------------------------------------
__global__ void __launch_bounds__(256) round_all(const float* __restrict__ x,
                                                 const float* __restrict__ y,
                                                 const float* __restrict__ W1,
                                                 float* __restrict__ out) {
    const int t = blockIdx.x * 256 + threadIdx.x;
    {
        float4 v = *(const float4*)&x[t * 4];
        v.x = to_tf32(v.x); v.y = to_tf32(v.y);
        v.z = to_tf32(v.z); v.w = to_tf32(v.w);
        *(float4*)&g_xr[t * 4] = v;
    }
    {
        float4 u = *(const float4*)&y[t * 4];
        u.x = to_tf32(u.x); u.y = to_tf32(u.y);
        u.z = to_tf32(u.z); u.w = to_tf32(u.w);
        *(float4*)&g_yr[t * 4] = u;
    }
    {
        float4 w = *(const float4*)&W1[t * 4];
        w.x = to_tf32(w.x); w.y = to_tf32(w.y);
        w.z = to_tf32(w.z); w.w = to_tf32(w.w);
        *(float4*)&g_Wr[t * 4] = w;
    }
    float4 z4 = make_float4(0.f, 0.f, 0.f, 0.f);
    *(float4*)&out[t * 8] = z4;
    *(float4*)&out[t * 8 + 4] = z4;
}

// -------------------------------------------------------------------------
// Tensor-core GEMM: C[m][n] = sum_k A[m][k]*W[k][n] via tf32 m16n8k8.
// 64x64 block tile, 256 threads = 8 warps x (32x16) warp tiles ->
// 16 warps/SM at 2 blocks, double the latency hiding of the 128-thr form.
// Ws[k][n] k-major stride 72 (b-frag banks (8*tig+g)%32 distinct).
// -------------------------------------------------------------------------
__global__ void __launch_bounds__(256, 3) gemm_tc() {
    const int z = blockIdx.z;
    const float* __restrict__ A = (z == 0) ? g_xr : g_yr;
    const float* __restrict__ W = g_Wr + z * DIM * DIM;
    float* __restrict__ C = (z == 0) ? g_hx : g_hy;

    __shared__ float As[2][64][36];
    __shared__ float Ws[2][32][72];

    const int tid  = threadIdx.x;
    const int wid  = tid >> 5;
    const int lane = tid & 31;
    const int g    = lane >> 2;    // 0..7
    const int tig  = lane & 3;     // 0..3
    const int wm   = (wid & 1) * 32;
    const int wn   = (wid >> 1) * 16;     // 0,16,32,48
    const int m0 = blockIdx.y * 64;
    const int n0 = blockIdx.x * 64;

    // A loader: 64 rows x 8 16B-chunks = 512 -> 2 per thread
    const int lrow = tid >> 2;
    const int lcp  = (tid & 3) * 2;
    // B loader: 32 k-rows x 16 16B-chunks = 512 -> 2 per thread
    const int brow = tid >> 3;
    const int bcp  = (tid & 7) * 2;

    uint32_t sAs[2], sWs[2];
    sAs[0] = (uint32_t)__cvta_generic_to_shared(&As[0][0][0]);
    sAs[1] = (uint32_t)__cvta_generic_to_shared(&As[1][0][0]);
    sWs[0] = (uint32_t)__cvta_generic_to_shared(&Ws[0][0][0]);
    sWs[1] = (uint32_t)__cvta_generic_to_shared(&Ws[1][0][0]);

    float c[2][2][4];
#pragma unroll
    for (int mi = 0; mi < 2; mi++)
#pragma unroll
        for (int nj = 0; nj < 2; nj++)
#pragma unroll
            for (int q = 0; q < 4; q++) c[mi][nj][q] = 0.0f;

    auto issue = [&](int bf, int k0) {
#pragma unroll
        for (int q = 0; q < 2; q++) {
            const int ch = lcp + q;
            cpa16_ca(sAs[bf] + (lrow * 36 + ch * 4) * 4,
                     &A[(m0 + lrow) * DIM + k0 + ch * 4]);
        }
#pragma unroll
        for (int q = 0; q < 2; q++) {
            const int ch = bcp + q;
            cpa16_ca(sWs[bf] + (brow * 72 + ch * 4) * 4,
                     &W[(k0 + brow) * DIM + n0 + ch * 4]);
        }
    };

    issue(0, 0);
    CP_COMMIT();

    for (int k0i = 0; k0i < 16; k0i++) {
        const int buf = k0i & 1;
        if (k0i < 15) {
            issue(buf ^ 1, (k0i + 1) * 32);
            CP_COMMIT();
            CP_WAIT(1);
        } else {
            CP_WAIT(0);
        }
        __syncthreads();

#pragma unroll
        for (int ks = 0; ks < 4; ks++) {
            const int kb = ks * 8;
            uint32_t a[2][4], b[2][2];
#pragma unroll
            for (int mi = 0; mi < 2; mi++) {
                const int r = wm + mi * 16 + g;
                a[mi][0] = __float_as_uint(As[buf][r][kb + tig]);
                a[mi][1] = __float_as_uint(As[buf][r + 8][kb + tig]);
                a[mi][2] = __float_as_uint(As[buf][r][kb + 4 + tig]);
                a[mi][3] = __float_as_uint(As[buf][r + 8][kb + 4 + tig]);
            }
#pragma unroll
            for (int nj = 0; nj < 2; nj++) {
                const int n = wn + nj * 8 + g;
                b[nj][0] = __float_as_uint(Ws[buf][kb + tig][n]);
                b[nj][1] = __float_as_uint(Ws[buf][kb + 4 + tig][n]);
            }
#pragma unroll
            for (int mi = 0; mi < 2; mi++)
#pragma unroll
                for (int nj = 0; nj < 2; nj++)
                    MMA_TF32(c[mi][nj], a[mi], b[nj]);
        }
        __syncthreads();
    }

#pragma unroll
    for (int mi = 0; mi < 2; mi++)
#pragma unroll
        for (int nj = 0; nj < 2; nj++) {
            const int r  = m0 + wm + mi * 16 + g;
            const int cc = n0 + wn + nj * 8 + 2 * tig;
            *(float2*)&C[r * DIM + cc] = make_float2(c[mi][nj][0], c[mi][nj][1]);
            *(float2*)&C[(r + 8) * DIM + cc] = make_float2(c[mi][nj][2], c[mi][nj][3]);
        }
}

// -------------------------------------------------------------------------
// Pairwise: out[i][j] += sum_{d in half z} relu(hx[i][d]+hy[j][d]) * w2[d]
// 64x64 tile, z-split -> 512 blocks. ti-major inner loop trims the a-frag
// live range -> ~64 regs -> 4 blocks/SM (8 warps/SMSP).
// -------------------------------------------------------------------------
__global__ void __launch_bounds__(256, 4) pairwise_kernel(const float* __restrict__ w2,
                                                          float* __restrict__ out) {
    __shared__ float xs[2][64][36];
    __shared__ float ys[2][64][36];
    __shared__ float w2s[DHALF];

    const int tid = threadIdx.x;
    const int tx = tid & 15;
    const int ty = tid >> 4;
    const int i0 = blockIdx.y * 64;
    const int j0 = blockIdx.x * 64;
    const int dbase = blockIdx.z * DHALF;

    const int lr = tid >> 3;
    const int lc = tid & 7;

    uint32_t sxs[2], sys[2];
    sxs[0] = (uint32_t)__cvta_generic_to_shared(&xs[0][0][0]);
    sxs[1] = (uint32_t)__cvta_generic_to_shared(&xs[1][0][0]);
    sys[0] = (uint32_t)__cvta_generic_to_shared(&ys[0][0][0]);
    sys[1] = (uint32_t)__cvta_generic_to_shared(&ys[1][0][0]);

    u64 acc[4][4];
#pragma unroll
    for (int i = 0; i < 4; i++)
#pragma unroll
        for (int j = 0; j < 4; j++) acc[i][j] = 0ULL;

    if (tid < 64)
        *(float4*)&w2s[tid * 4] = *(const float4*)&w2[dbase + tid * 4];

    auto issue = [&](int bf, int dg) {
#pragma unroll
        for (int it = 0; it < 2; it++) {
            cpa16_ca(sxs[bf] + ((lr + it * 32) * 36 + lc * 4) * 4,
                     &g_hx[(i0 + lr + it * 32) * DIM + dbase + dg + lc * 4]);
            cpa16_ca(sys[bf] + ((lr + it * 32) * 36 + lc * 4) * 4,
                     &g_hy[(j0 + lr + it * 32) * DIM + dbase + dg + lc * 4]);
        }
    };

    issue(0, 0);
    CP_COMMIT();

    for (int chk = 0; chk < 8; chk++) {
        const int buf = chk & 1;
        if (chk < 7) {
            issue(buf ^ 1, (chk + 1) * 32);
            CP_COMMIT();
            CP_WAIT(1);
        } else {
            CP_WAIT(0);
        }
        __syncthreads();

        const float* __restrict__ w2p = &w2s[chk * 32];
#pragma unroll
        for (int dd = 0; dd < 32; dd += 4) {
            ulonglong2 bv[4];
#pragma unroll
            for (int tj = 0; tj < 4; tj++)
                bv[tj] = *(const ulonglong2*)&ys[buf][tx + 16 * tj][dd];
            ulonglong2 wv = *(const ulonglong2*)&w2p[dd];
#pragma unroll
            for (int ti = 0; ti < 4; ti++) {
                ulonglong2 av = *(const ulonglong2*)&xs[buf][ty + 16 * ti][dd];
#pragma unroll
                for (int tj = 0; tj < 4; tj++) {
                    u64 s0, s1;
                    ADD2(s0, av.x, bv[tj].x);
                    s0 = relu2(s0);
                    FMA2(acc[ti][tj], s0, wv.x, acc[ti][tj]);
                    ADD2(s1, av.y, bv[tj].y);
                    s1 = relu2(s1);
                    FMA2(acc[ti][tj], s1, wv.y, acc[ti][tj]);
                }
            }
        }
        __syncthreads();
    }

#pragma unroll
    for (int ti = 0; ti < 4; ti++)
#pragma unroll
        for (int tj = 0; tj < 4; tj++)
            atomicAdd(&out[(i0 + ty + 16 * ti) * MROWS + j0 + tx + 16 * tj],
                      hsum2(acc[ti][tj]));
}

extern "C" void kernel_launch(void* const* d_in, const int* in_sizes, int n_in,
                              void* d_out, int out_size) {
    const float* x  = (const float*)d_in[0];
    const float* y  = (const float*)d_in[1];
    const float* W1 = (const float*)d_in[2];
    const float* W2 = (const float*)d_in[3];
    float* out = (float*)d_out;

    round_all<<<512, 256>>>(x, y, W1, out);

    dim3 ggrid(DIM / 64, NROWS / 64, 2);     // 256 blocks, 256 thr
    gemm_tc<<<ggrid, 256>>>();

    dim3 pgrid(MROWS / 64, NROWS / 64, 2);   // 512 blocks
    pairwise_kernel<<<pgrid, 256>>>(W2, out);
}